// round 10
// baseline (speedup 1.0000x reference)
#include <cuda_runtime.h>
#include <cuda.h>
#include <cstdint>

// FilterLayer: y[b,c,h,w] = sum_{i,j in 5x5} x_pad[b,c,h+i,w+j] * f[b,i*5+j,h,w]
// B=4, C=3, H=W=512, window=5, zero pad 2.
// R8: TMA (UTMALDG) pipeline for the dominant 105MB f stream. LDG-path BW is
// capped ~4.5TB/s by the per-SM L1tex outstanding-wavefront queue; TMA requests
// are tracked by mbarrier complete_tx, not that queue. Stage = one filter row
// (box [64,8,5] = 10KB) in ONE TMA instruction; 3-buffer ring, depth 2.
// Compute identical to R4: 2px/thread float2, conflict-free LDS.

#define IMG_H 512
#define IMG_W 512
#define TWX 32
#define TH  8
#define TILE_W (TWX * 2)          // 64
#define HALO 2
#define TILE_R (TH + 2 * HALO)    // 12
#define TILE_C (TILE_W + 4)       // 68
#define NBUF 3
#define STAGE_FLOATS (5 * TH * TILE_W)        // 2560
#define STAGE_BYTES  (STAGE_FLOATS * 4)       // 10240

__device__ __forceinline__ uint32_t smem_u32(const void* p) {
    return (uint32_t)__cvta_generic_to_shared(p);
}
__device__ __forceinline__ void mbar_init(uint32_t mbar, uint32_t cnt) {
    asm volatile("mbarrier.init.shared.b64 [%0], %1;" :: "r"(mbar), "r"(cnt) : "memory");
}
__device__ __forceinline__ void mbar_expect_tx(uint32_t mbar, uint32_t bytes) {
    asm volatile("mbarrier.arrive.expect_tx.shared.b64 _, [%0], %1;"
                 :: "r"(mbar), "r"(bytes) : "memory");
}
__device__ __forceinline__ void mbar_wait(uint32_t mbar, uint32_t parity) {
    uint32_t done;
    asm volatile(
        "{\n\t.reg .pred p;\n\t"
        "mbarrier.try_wait.parity.acquire.cta.shared::cta.b64 p, [%1], %2;\n\t"
        "selp.b32 %0, 1, 0, p;\n\t}"
        : "=r"(done) : "r"(mbar), "r"(parity) : "memory");
    if (!done) {
        asm volatile(
            "{\n\t.reg .pred P1;\n\t"
            "W_%=:\n\t"
            "mbarrier.try_wait.parity.acquire.cta.shared::cta.b64 P1, [%0], %1, 0x989680;\n\t"
            "@P1 bra.uni D_%=;\n\t"
            "bra.uni W_%=;\n\t"
            "D_%=:\n\t}"
            :: "r"(mbar), "r"(parity) : "memory");
    }
}
__device__ __forceinline__ void tma_load_3d(uint32_t dst, const CUtensorMap* tmap,
                                            int cx, int cy, int cz, uint32_t mbar) {
    asm volatile(
        "cp.async.bulk.tensor.3d.shared::cta.global.tile.mbarrier::complete_tx::bytes "
        "[%0], [%1, {%2, %3, %4}], [%5];"
        :: "r"(dst), "l"(tmap), "r"(cx), "r"(cy), "r"(cz), "r"(mbar) : "memory");
}

__global__ __launch_bounds__(256)
void filter_layer_kernel(const __grid_constant__ CUtensorMap tmap_f,
                         const float* __restrict__ x,
                         float* __restrict__ out)
{
    // fs[buf][j-tap][row][col]; TMA fills a whole buf per stage
    __shared__ __align__(1024) float fs[NBUF][5][TH][TILE_W];   // 30 KB
    __shared__ __align__(8)    float xs[3][TILE_R][TILE_C];     // 9.8 KB
    __shared__ __align__(8)    unsigned long long mbar[NBUF];

    const int b   = blockIdx.z;
    const int w0  = blockIdx.x * TILE_W;
    const int h0  = blockIdx.y * TH;
    const int tx  = threadIdx.x;
    const int ty  = threadIdx.y;
    const int tid = ty * TWX + tx;

    const int HW = IMG_H * IMG_W;
    const int plane0 = b * 25;

    if (tid == 0) {
        #pragma unroll
        for (int s = 0; s < NBUF; ++s) mbar_init(smem_u32(&mbar[s]), 1);
    }
    __syncthreads();

    // ---- prologue: issue TMA stages 0 and 1 (one instruction each) ----
    if (tid == 0) {
        #pragma unroll
        for (int s = 0; s < 2; ++s) {
            uint32_t mb = smem_u32(&mbar[s]);
            mbar_expect_tx(mb, STAGE_BYTES);
            tma_load_3d(smem_u32(&fs[s][0][0][0]), &tmap_f, w0, h0, plane0 + 5 * s, mb);
        }
    }

    // ---- stage x tile via LDG (12.6MB total, L2-resident) ----
    const float* xb = x + (size_t)b * 3 * HW;
    for (int idx = tid; idx < 3 * TILE_R * TILE_C; idx += 256) {
        int c   = idx / (TILE_R * TILE_C);
        int rem = idx - c * (TILE_R * TILE_C);
        int r   = rem / TILE_C;
        int col = rem - r * TILE_C;
        int gr  = h0 + r - HALO;
        int gc  = w0 + col - HALO;
        float v = 0.0f;
        if ((unsigned)gr < (unsigned)IMG_H && (unsigned)gc < (unsigned)IMG_W)
            v = __ldg(xb + c * HW + gr * IMG_W + gc);
        xs[c][r][col] = v;
    }
    __syncthreads();

    const int p0 = 2 * tx;
    float2 a0 = make_float2(0.f, 0.f);
    float2 a1 = a0, a2 = a0;

    #pragma unroll
    for (int i = 0; i < 5; ++i) {
        mbar_wait(smem_u32(&mbar[i % NBUF]), i / NBUF);

        // x row i: 6 consecutive floats per channel, 8B-aligned -> 3x LDS.64
        float xr0[6], xr1[6], xr2[6];
        {
            const float2* r0 = (const float2*)&xs[0][ty + i][p0];
            const float2* r1 = (const float2*)&xs[1][ty + i][p0];
            const float2* r2 = (const float2*)&xs[2][ty + i][p0];
            float2 u;
            u = r0[0]; xr0[0]=u.x; xr0[1]=u.y;
            u = r0[1]; xr0[2]=u.x; xr0[3]=u.y;
            u = r0[2]; xr0[4]=u.x; xr0[5]=u.y;
            u = r1[0]; xr1[0]=u.x; xr1[1]=u.y;
            u = r1[1]; xr1[2]=u.x; xr1[3]=u.y;
            u = r1[2]; xr1[4]=u.x; xr1[5]=u.y;
            u = r2[0]; xr2[0]=u.x; xr2[1]=u.y;
            u = r2[1]; xr2[2]=u.x; xr2[3]=u.y;
            u = r2[2]; xr2[4]=u.x; xr2[5]=u.y;
        }

        const int buf = i % NBUF;
        #pragma unroll
        for (int j = 0; j < 5; ++j) {
            const float2 fv = *(const float2*)&fs[buf][j][ty][p0];
            a0.x = fmaf(xr0[j    ], fv.x, a0.x);
            a0.y = fmaf(xr0[j + 1], fv.y, a0.y);
            a1.x = fmaf(xr1[j    ], fv.x, a1.x);
            a1.y = fmaf(xr1[j + 1], fv.y, a1.y);
            a2.x = fmaf(xr2[j    ], fv.x, a2.x);
            a2.y = fmaf(xr2[j + 1], fv.y, a2.y);
        }

        // all warps finished consuming stage i (hence also i-1) -> safe to
        // overwrite buf (i+2)%NBUF (last used by stage i-1)
        __syncthreads();
        if (i + 2 < 5 && tid == 0) {
            const int s  = i + 2;
            uint32_t mb = smem_u32(&mbar[s % NBUF]);
            mbar_expect_tx(mb, STAGE_BYTES);
            tma_load_3d(smem_u32(&fs[s % NBUF][0][0][0]), &tmap_f,
                        w0, h0, plane0 + 5 * s, mb);
        }
    }

    // streaming stores (out written once; keep L2 for x)
    const int h   = h0 + ty;
    const int W2  = IMG_W / 2;
    const int HW2 = HW / 2;
    float2* o2 = (float2*)(out + (size_t)b * 3 * HW);
    const int obase = h * W2 + (w0 >> 1) + tx;
    __stcs(o2 + obase,           a0);
    __stcs(o2 + obase + HW2,     a1);
    __stcs(o2 + obase + 2 * HW2, a2);
}

typedef CUresult (*PFN_encodeTiled_t)(
    CUtensorMap*, CUtensorMapDataType, cuuint32_t, void*,
    const cuuint64_t*, const cuuint64_t*, const cuuint32_t*, const cuuint32_t*,
    CUtensorMapInterleave, CUtensorMapSwizzle, CUtensorMapL2promotion,
    CUtensorMapFloatOOBfill);

extern "C" void kernel_launch(void* const* d_in, const int* in_sizes, int n_in,
                              void* d_out, int out_size)
{
    const float* x = (const float*)d_in[0];
    float* f       = (float*)d_in[1];
    float* out     = (float*)d_out;

    // Build the f tensor map on the host stack (pure host work; capture-safe,
    // no allocations). Resolve the driver symbol through cudart so we do not
    // depend on -lcuda at link time.
    PFN_encodeTiled_t encode = nullptr;
    cudaDriverEntryPointQueryResult st;
    cudaGetDriverEntryPoint("cuTensorMapEncodeTiled", (void**)&encode,
                            cudaEnableDefault, &st);

    CUtensorMap tmap{};
    // f viewed as [planes=100][H=512][W=512], row-major
    cuuint64_t dims[3]    = {IMG_W, IMG_H, 100};
    cuuint64_t strides[2] = {IMG_W * sizeof(float),
                             (cuuint64_t)IMG_H * IMG_W * sizeof(float)};
    cuuint32_t box[3]     = {TILE_W, TH, 5};
    cuuint32_t estr[3]    = {1, 1, 1};
    encode(&tmap, CU_TENSOR_MAP_DATA_TYPE_FLOAT32, 3, f,
           dims, strides, box, estr,
           CU_TENSOR_MAP_INTERLEAVE_NONE, CU_TENSOR_MAP_SWIZZLE_NONE,
           CU_TENSOR_MAP_L2_PROMOTION_L2_128B, CU_TENSOR_MAP_FLOAT_OOB_FILL_NONE);

    dim3 block(TWX, TH, 1);                        // 256 threads
    dim3 grid(IMG_W / TILE_W, IMG_H / TH, 4);      // 8 x 64 x 4 = 2048 blocks
    filter_layer_kernel<<<grid, block>>>(tmap, x, out);
}